// round 16
// baseline (speedup 1.0000x reference)
#include <cuda_runtime.h>
#include <math.h>
#include <math_constants.h>

#define Uu    128
#define Nn    512
#define Ff    80
#define FUF   64
#define TOPK  10
#define EPSV  1e-10f
#define C10L2E 14.4269504088896340736f   // 10 * log2(e)
#define L2E    1.44269504088896340736f
#define THRX   18.0f                     // cutoff in ex2-arg units (validated R14)

__device__ __forceinline__ float ex2(float x) {
    float r;
    asm("ex2.approx.ftz.f32 %0, %1;" : "=f"(r) : "f"(x));
    return r;
}
__device__ __forceinline__ float warp_sum(float v) {
#pragma unroll
    for (int o = 16; o > 0; o >>= 1) v += __shfl_xor_sync(0xffffffffu, v, o);
    return v;
}

// warp-collective repeated argmax (value desc, index asc) over vals[0..511]
__device__ __forceinline__ void warp_top10_vals(const float* vals, int lane, float* outv) {
    float mv[16];
#pragma unroll
    for (int k = 0; k < 16; k++) mv[k] = vals[(k << 5) + lane];
    for (int t = 0; t < TOPK; t++) {
        float bv = -CUDART_INF_F; int bi = Nn;
#pragma unroll
        for (int k = 0; k < 16; k++) {
            int j = (k << 5) + lane;
            if (mv[k] > bv || (mv[k] == bv && j < bi)) { bv = mv[k]; bi = j; }
        }
#pragma unroll
        for (int o = 16; o > 0; o >>= 1) {
            float ov = __shfl_xor_sync(0xffffffffu, bv, o);
            int   oi = __shfl_xor_sync(0xffffffffu, bi, o);
            if (ov > bv || (ov == bv && oi < bi)) { bv = ov; bi = oi; }
        }
        outv[t] = bv;
        if ((bi & 31) == lane) mv[bi >> 5] = -CUDART_INF_F;
    }
}

__global__ void __launch_bounds__(512, 2) mega_kernel(
    const float* __restrict__ batch, const float* __restrict__ s_div,
    const float* __restrict__ s_ndcg, const float* __restrict__ rel_g,
    float* __restrict__ out)
{
    __shared__ float  ssc[Nn];                 // raw scores by orig idx (sort compares)
    __shared__ float  ssort[Nn];               // sorted scores
    __shared__ float2 sTB[Nn + 8];             // (s*C, -A*C) per sorted column (+guard)
    __shared__ float2 srm[Nn + 8];             // (rho, mxx) per row (+guard)
    __shared__ int    sidx[Nn];
    __shared__ float  sc[Nn + 8];
    __shared__ int    slo[Nn], shi[Nn];        // band edges per row
    __shared__ int    srlo[Nn], srhi[Nn];      // row range per column (scatter-inverted)
    __shared__ float  reg6[2][Nn];             // ndcg: rel_sorted / rel_raw ; div: rank / mask
    __shared__ float  swarp[16];
    __shared__ float  sarel[TOPK], st10b[TOPK];
    __shared__ float  sgp[16][FUF], shp[16][FUF];
    __shared__ float  sscal[16][4];
    __shared__ float  sfin[2 * FUF];

    int bid = blockIdx.x;
    bool isdiv = bid >= Uu;                    // MIXED pairing: co-resident (b, b+148)
    int u = isdiv ? bid - Uu : bid;            // = one ndcg + one div block per SM
    int tid = threadIdx.x, w = tid >> 5, lane = tid & 31;

    // ---------------- setup
    const float* sp = isdiv ? (s_div + (size_t)u * Nn) : (s_ndcg + (size_t)u * Nn);
    float myscore = sp[tid];
    ssc[tid] = myscore;
    float myrel = 0.f;
    if (!isdiv) { myrel = rel_g[(size_t)u * Nn + tid]; reg6[1][tid] = myrel; }
    if (tid < 8) {
        sTB[Nn + tid] = make_float2(0.f, -1e30f);   // guard: e -> ex2(-huge) = 0
        srm[Nn + tid] = make_float2(0.f, 1e30f);    // guard: rho=0, arg -> -huge
        sc[Nn + tid]  = 0.f;
    }
    __syncthreads();

    // ---------------- rank sort: float compares, float4 loads, tie by index
    {
        float s = myscore;
        int c0 = tid >> 2;
        const float4* fp = (const float4*)ssc;
        int rank = 0;
        for (int k2 = 0; k2 < c0; k2++) {                 // all k < tid: ties count
            float4 q = fp[k2];
            rank += (q.x <= s) + (q.y <= s) + (q.z <= s) + (q.w <= s);
        }
        {                                                  // boundary chunk
            float4 q = fp[c0];
            float qq[4] = {q.x, q.y, q.z, q.w};
            int base = c0 << 2;
#pragma unroll
            for (int c = 0; c < 4; c++) {
                int k = base + c;
                if (k < tid)      rank += (qq[c] <= s);
                else if (k > tid) rank += (qq[c] <  s);
            }
        }
        for (int k2 = c0 + 1; k2 < Nn / 4; k2++) {        // all k > tid: strict
            float4 q = fp[k2];
            rank += (q.x < s) + (q.y < s) + (q.z < s) + (q.w < s);
        }
        ssort[rank] = myscore;
        sidx[rank] = tid;
        if (!isdiv) reg6[0][rank] = myrel;                 // rel in sorted order
        else ((int*)reg6[1])[tid] = (rank >= Nn - TOPK) ? 1 : 0;   // top-10 mask
    }
    __syncthreads();

    // ---------------- prefix scan (warp shuffles), build TB
    {
        float x = ssort[tid];
        float inc = x;
#pragma unroll
        for (int o = 1; o < 32; o <<= 1) {
            float up = __shfl_up_sync(0xffffffffu, inc, o);
            if (lane >= o) inc += up;
        }
        if (lane == 31) swarp[w] = inc;
        __syncthreads();
        if (w == 0) {
            float t = (lane < 16) ? swarp[lane] : 0.f;
#pragma unroll
            for (int o = 1; o < 16; o <<= 1) {
                float up = __shfl_up_sync(0xffffffffu, t, o);
                if (lane >= o) t += up;
            }
            if (lane < 16) swarp[lane] = t;
        }
        __syncthreads();
        float offs = (w > 0) ? swarp[w - 1] : 0.f;
        float tot = swarp[15];
        float incl = inc + offs;
        float pre = incl - x;
        float A = (float)(2 * tid - Nn) * x + tot - 2.f * pre;
        sTB[tid] = make_float2(x * C10L2E, -A * C10L2E);
    }
    __syncthreads();

    // ---------------- per-row band: analytic peak j* = N-1-r, two binary searches
    float my_v = (float)(Nn - 1 - 2 * tid);
    float my_mxx;
    int my_lo, my_hi;
    {
        int jstar = Nn - 1 - tid;
        float2 tp = sTB[jstar];
        my_mxx = fmaf(my_v, tp.x, tp.y);       // exact row max (x unimodal, peak at jstar)
        float thr = my_mxx - THRX;
        int a0 = 0, b0 = jstar;                // x nondecreasing on [0, jstar]
        while (a0 < b0) {
            int m = (a0 + b0) >> 1;
            float2 t = sTB[m];
            if (fmaf(my_v, t.x, t.y) >= thr) b0 = m; else a0 = m + 1;
        }
        my_lo = a0;
        a0 = jstar; b0 = Nn - 1;               // x nonincreasing on [jstar, N-1]
        while (a0 < b0) {
            int m = (a0 + b0 + 1) >> 1;
            float2 t = sTB[m];
            if (fmaf(my_v, t.x, t.y) >= thr) a0 = m; else b0 = m - 1;
        }
        my_hi = a0 + 1;
        slo[tid] = my_lo; shi[tid] = my_hi;
    }
    __syncthreads();

    // ---------------- column row-ranges by scatter inversion (lo/hi monotone)
    {
        int prev = (tid == 0) ? Nn : slo[tid - 1];         // rlo(j) = tid for j in [lo, prev)
        for (int j = my_lo; j < prev; j++) srlo[j] = tid;
        int nxt = (tid == Nn - 1) ? 0 : shi[tid + 1];      // rhi(j) = tid for j in [nxt, hi)
        for (int j = nxt; j < my_hi; j++) srhi[j] = tid;
    }
    __syncthreads();

    int my_rlo = srlo[tid], my_rhi = srhi[tid];
    int my_lo8 = my_lo & ~7;
    int my_i0  = my_rlo & ~7;
    int my_nitA = (my_hi - my_lo8 + 7) >> 3;   // 8-wide iterations, pass A
    int my_nitB = (my_rhi - my_i0 + 8) >> 3;   // 8-wide iterations, pass B
    float2 my_tb = sTB[tid];
    float my_r = 1.0f, my_inv = 1.0f;

    // ---------------- sweeps
    // sweep 0: col#1 (r=1).  sweeps 1..4: row#k + col#(k+1).
    // sweep 5 (div only): weighted row#5 + approx_rank.  ndcg row#5 in tail.
    int nsweep = isdiv ? 6 : 5;
    for (int sweep = 0; sweep < nsweep; sweep++) {
        bool first = (sweep == 0);
        bool last6 = (sweep == 5);
        // ---- pass A: thread-per-row, 8-wide, pointer-increment addressing
        {
            float a0 = 0.f, a1 = 0.f, a2 = 0.f, a3 = 0.f;
            const float4* pt = (const float4*)&sTB[my_lo8];
            if (first) {
                for (int it = 0; it < my_nitA; it++) {
                    float4 t01 = pt[0], t23 = pt[1], t45 = pt[2], t67 = pt[3];
                    pt += 4;
                    a0 += ex2(fmaf(my_v, t01.x, t01.y) - my_mxx)
                        + ex2(fmaf(my_v, t45.x, t45.y) - my_mxx);
                    a1 += ex2(fmaf(my_v, t01.z, t01.w) - my_mxx)
                        + ex2(fmaf(my_v, t45.z, t45.w) - my_mxx);
                    a2 += ex2(fmaf(my_v, t23.x, t23.y) - my_mxx)
                        + ex2(fmaf(my_v, t67.x, t67.y) - my_mxx);
                    a3 += ex2(fmaf(my_v, t23.z, t23.w) - my_mxx)
                        + ex2(fmaf(my_v, t67.z, t67.w) - my_mxx);
                }
            } else {
                const float4* pc = (const float4*)&sc[my_lo8];
                for (int it = 0; it < my_nitA; it++) {
                    float4 t01 = pt[0], t23 = pt[1], t45 = pt[2], t67 = pt[3];
                    float4 cA = pc[0], cB = pc[1];
                    pt += 4; pc += 2;
                    a0 = fmaf(cA.x, ex2(fmaf(my_v, t01.x, t01.y) - my_mxx), a0);
                    a1 = fmaf(cA.y, ex2(fmaf(my_v, t01.z, t01.w) - my_mxx), a1);
                    a2 = fmaf(cA.z, ex2(fmaf(my_v, t23.x, t23.y) - my_mxx), a2);
                    a3 = fmaf(cA.w, ex2(fmaf(my_v, t23.z, t23.w) - my_mxx), a3);
                    a0 = fmaf(cB.x, ex2(fmaf(my_v, t45.x, t45.y) - my_mxx), a0);
                    a1 = fmaf(cB.y, ex2(fmaf(my_v, t45.z, t45.w) - my_mxx), a1);
                    a2 = fmaf(cB.z, ex2(fmaf(my_v, t67.x, t67.y) - my_mxx), a2);
                    a3 = fmaf(cB.w, ex2(fmaf(my_v, t67.z, t67.w) - my_mxx), a3);
                }
            }
            float racc = (a0 + a1) + (a2 + a3);
            float rho;
            if (first) {
                my_inv = 1.f / racc;           // racc >= 1 (exp at jstar == 1)
                rho = my_inv;
            } else {
                float rowsum = my_inv * racc;
                float rn = (rowsum == 0.f) ? 0.f : (my_r / fmaxf(my_r * rowsum, EPSV));
                if (!last6) my_r = rn;
                rho = rn * my_inv;
                if (last6) rho *= (float)(Nn - tid);   // w_i = N - i
            }
            srm[tid] = make_float2(rho, my_mxx);
        }
        __syncthreads();
        // ---- pass B: thread-per-column, 8-wide, pointer-increment addressing
        {
            float a0 = 0.f, a1 = 0.f, a2 = 0.f, a3 = 0.f;
            float vf0 = (float)(Nn - 1 - 2 * my_i0);
            const float4* pr = (const float4*)&srm[my_i0];
            for (int it = 0; it < my_nitB; it++) {
                float4 r01 = pr[0], r23 = pr[1], r45 = pr[2], r67 = pr[3];
                pr += 4;
                a0 = fmaf(r01.x, ex2(fmaf(vf0,        my_tb.x, my_tb.y) - r01.y), a0);
                a1 = fmaf(r01.z, ex2(fmaf(vf0 -  2.f, my_tb.x, my_tb.y) - r01.w), a1);
                a2 = fmaf(r23.x, ex2(fmaf(vf0 -  4.f, my_tb.x, my_tb.y) - r23.y), a2);
                a3 = fmaf(r23.z, ex2(fmaf(vf0 -  6.f, my_tb.x, my_tb.y) - r23.w), a3);
                a0 = fmaf(r45.x, ex2(fmaf(vf0 -  8.f, my_tb.x, my_tb.y) - r45.y), a0);
                a1 = fmaf(r45.z, ex2(fmaf(vf0 - 10.f, my_tb.x, my_tb.y) - r45.w), a1);
                a2 = fmaf(r67.x, ex2(fmaf(vf0 - 12.f, my_tb.x, my_tb.y) - r67.y), a2);
                a3 = fmaf(r67.z, ex2(fmaf(vf0 - 14.f, my_tb.x, my_tb.y) - r67.w), a3);
                vf0 -= 16.f;
            }
            float cac = (a0 + a1) + (a2 + a3);
            if (!last6) {
                float c = first ? 1.f : sc[tid];
                sc[tid] = (cac == 0.f) ? 0.f : (c / fmaxf(c * cac, EPSV));
            } else {
                float arr = sc[tid] * cac;     // approx_rank (sorted col)
                reg6[0][sidx[tid]] = 1.f / (1.f + ex2(((float)(Nn - TOPK) - arr) * L2E));
            }
        }
        __syncthreads();
    }

    // ---------------- finals
    if (!isdiv) {
        // row#5 for rows 0..9 only, fused with approx_rel (thread-per-row)
        if (tid < TOPK) {
            float racc = 0.f, ra = 0.f;
            for (int j = my_lo8; j < my_hi; j += 2) {
                float4 t01 = *(const float4*)&sTB[j];
                float c0 = sc[j], c1 = sc[j + 1];
                float e0 = c0 * ex2(fmaf(my_v, t01.x, t01.y) - my_mxx);
                float e1 = c1 * ex2(fmaf(my_v, t01.z, t01.w) - my_mxx);
                racc += e0 + e1;
                ra = fmaf(e0, reg6[0][j], ra);
                ra = fmaf(e1, (j + 1 < Nn) ? reg6[0][j + 1] : 0.f, ra);
            }
            float rowsum = my_inv * racc;
            float rn = (rowsum == 0.f) ? 0.f : (my_r / fmaxf(my_r * rowsum, EPSV));
            sarel[tid] = rn * my_inv * ra;
        }
        if (w == 2) warp_top10_vals(reg6[1], lane, st10b);   // top-10 of relevance
        __syncthreads();
        if (tid == 0) {
            float da = 0.f, dm = 0.f, db = 0.f;
            for (int t = 0; t < TOPK; t++) {
                float disc = log2f((float)(t + 2));
                da += (exp2f(sarel[t]) - 1.f) / disc;
                dm += (exp2f(reg6[0][Nn - 1 - t]) - 1.f) / disc;  // rel at top-10 scores
                db += (exp2f(st10b[t]) - 1.f) / disc;
            }
            out[u]      = da / db;
            out[Uu + u] = dm / db;
        }
    } else {
        // item phase: warp per 32 items, lane owns feats {2l, 2l+1}
        float gx = 0.f, gy = 0.f, hx = 0.f, hy = 0.f;
        float s1 = 0.f, s2 = 0.f, q = 0.f, qh = 0.f;
        for (int ii = 0; ii < 32; ii++) {
            int j = (w << 5) + ii;
            const float2 xy = *(const float2*)(batch + ((size_t)(u * Nn + j)) * Ff + 2 * lane);
            float nr = xy.x * xy.x + xy.y * xy.y;
            nr = warp_sum(nr);
            float nrm = sqrtf(nr);
            float inv = 1.f / fmaxf(nrm, 1e-8f);
            float nn = nr * inv * inv;
            float a = reg6[0][j];
            gx += a * xy.x * inv; gy += a * xy.y * inv;
            int m = ((int*)reg6[1])[j];
            if (m) { hx += xy.x * inv; hy += xy.y * inv; }
            if (lane == 0) {
                s1 += a; s2 += a * a; q += a * a * nn;
                if (m) qh += nn;
            }
        }
        sgp[w][2 * lane] = gx; sgp[w][2 * lane + 1] = gy;
        shp[w][2 * lane] = hx; shp[w][2 * lane + 1] = hy;
        if (lane == 0) {
            sscal[w][0] = s1; sscal[w][1] = s2; sscal[w][2] = q; sscal[w][3] = qh;
        }
        __syncthreads();
        if (tid < FUF) {
            float gf = 0.f, hf = 0.f;
#pragma unroll
            for (int qq = 0; qq < 16; qq++) { gf += sgp[qq][tid]; hf += shp[qq][tid]; }
            sfin[tid] = gf * gf;
            sfin[FUF + tid] = hf * hf;
        }
        __syncthreads();
        if (tid == 0) {
            float G2 = 0.f, H2 = 0.f;
            for (int f = 0; f < FUF; f++) { G2 += sfin[f]; H2 += sfin[FUF + f]; }
            float S1 = 0.f, S2v = 0.f, Q = 0.f, Qh = 0.f;
            for (int qq = 0; qq < 16; qq++) {
                S1 += sscal[qq][0]; S2v += sscal[qq][1];
                Q  += sscal[qq][2]; Qh  += sscal[qq][3];
            }
            float denomA = S1 * S1 - S2v;
            out[2 * Uu + u] = 1.f - (G2 - Q) / denomA;
            out[3 * Uu + u] = (45.f - 0.5f * (H2 - Qh)) / 45.f;
        }
    }
}

// ---------------------------------------------------------------------------
extern "C" void kernel_launch(void* const* d_in, const int* in_sizes, int n_in,
                              void* d_out, int out_size) {
    const float* batch  = (const float*)d_in[0];
    const float* s_div  = (const float*)d_in[1];
    const float* s_ndcg = (const float*)d_in[2];
    const float* rel    = (const float*)d_in[3];
    float* out = (float*)d_out;

    mega_kernel<<<256, 512>>>(batch, s_div, s_ndcg, rel, out);
}

// round 17
// speedup vs baseline: 1.1071x; 1.1071x over previous
#include <cuda_runtime.h>
#include <math.h>
#include <math_constants.h>

#define Uu    128
#define Nn    512
#define Ff    80
#define FUF   64
#define TOPK  10
#define EPSV  1e-10f
#define C10L2E 14.4269504088896340736f   // 10 * log2(e)
#define L2E    1.44269504088896340736f
#define THRX   13.0f                     // cutoff in ex2-arg units

__device__ __forceinline__ float ex2(float x) {
    float r;
    asm("ex2.approx.ftz.f32 %0, %1;" : "=f"(r) : "f"(x));
    return r;
}
__device__ __forceinline__ float warp_sum(float v) {
#pragma unroll
    for (int o = 16; o > 0; o >>= 1) v += __shfl_xor_sync(0xffffffffu, v, o);
    return v;
}

// warp-collective repeated argmax (value desc, index asc) over vals[0..511]
__device__ __forceinline__ void warp_top10_vals(const float* vals, int lane, float* outv) {
    float mv[16];
#pragma unroll
    for (int k = 0; k < 16; k++) mv[k] = vals[(k << 5) + lane];
    for (int t = 0; t < TOPK; t++) {
        float bv = -CUDART_INF_F; int bi = Nn;
#pragma unroll
        for (int k = 0; k < 16; k++) {
            int j = (k << 5) + lane;
            if (mv[k] > bv || (mv[k] == bv && j < bi)) { bv = mv[k]; bi = j; }
        }
#pragma unroll
        for (int o = 16; o > 0; o >>= 1) {
            float ov = __shfl_xor_sync(0xffffffffu, bv, o);
            int   oi = __shfl_xor_sync(0xffffffffu, bi, o);
            if (ov > bv || (ov == bv && oi < bi)) { bv = ov; bi = oi; }
        }
        outv[t] = bv;
        if ((bi & 31) == lane) mv[bi >> 5] = -CUDART_INF_F;
    }
}

__global__ void __launch_bounds__(512, 2) mega_kernel(
    const float* __restrict__ batch, const float* __restrict__ s_div,
    const float* __restrict__ s_ndcg, const float* __restrict__ rel_g,
    float* __restrict__ out)
{
    __shared__ float  ssc[Nn];                 // raw scores by orig idx (sort compares)
    __shared__ float  ssort[Nn];               // sorted scores
    __shared__ float2 sTB[Nn + 8];             // (s*C, -A*C) per sorted column (+guard)
    __shared__ float2 srm[Nn + 8];             // (rho, mxx) per row (+guard)
    __shared__ int    sidx[Nn];
    __shared__ float  sc[Nn + 8];
    __shared__ int    slo[Nn], shi[Nn];        // band edges per row
    __shared__ int    srlo[Nn], srhi[Nn];      // row range per column (scatter-inverted)
    __shared__ float  reg6[2][Nn];             // ndcg: rel_sorted / rel_raw ; div: rank / mask
    __shared__ float  swarp[16];
    __shared__ float  sarel[TOPK], st10b[TOPK];
    __shared__ float  sgp[16][FUF], shp[16][FUF];
    __shared__ float  sscal[16][4];
    __shared__ float  sfin[2 * FUF];

    int bid = blockIdx.x;
    int u = bid >> 1;                          // proven same-type pairing (58.4us run)
    bool isdiv = (bid & 1) != 0;
    int tid = threadIdx.x, w = tid >> 5, lane = tid & 31;

    // ---------------- setup
    const float* sp = isdiv ? (s_div + (size_t)u * Nn) : (s_ndcg + (size_t)u * Nn);
    float myscore = sp[tid];
    ssc[tid] = myscore;
    float myrel = 0.f;
    if (!isdiv) { myrel = rel_g[(size_t)u * Nn + tid]; reg6[1][tid] = myrel; }
    if (tid < 8) {
        sTB[Nn + tid] = make_float2(0.f, -1e30f);   // guard: e -> ex2(-huge) = 0
        srm[Nn + tid] = make_float2(0.f, 1e30f);    // guard: rho=0, arg -> -huge
        sc[Nn + tid]  = 0.f;
    }
    __syncthreads();

    // ---------------- rank sort: float compares, float4 loads, tie by index
    {
        float s = myscore;
        int c0 = tid >> 2;
        const float4* fp = (const float4*)ssc;
        int rank = 0;
        for (int k2 = 0; k2 < c0; k2++) {                 // all k < tid: ties count
            float4 q = fp[k2];
            rank += (q.x <= s) + (q.y <= s) + (q.z <= s) + (q.w <= s);
        }
        {                                                  // boundary chunk
            float4 q = fp[c0];
            float qq[4] = {q.x, q.y, q.z, q.w};
            int base = c0 << 2;
#pragma unroll
            for (int c = 0; c < 4; c++) {
                int k = base + c;
                if (k < tid)      rank += (qq[c] <= s);
                else if (k > tid) rank += (qq[c] <  s);
            }
        }
        for (int k2 = c0 + 1; k2 < Nn / 4; k2++) {        // all k > tid: strict
            float4 q = fp[k2];
            rank += (q.x < s) + (q.y < s) + (q.z < s) + (q.w < s);
        }
        ssort[rank] = myscore;
        sidx[rank] = tid;
        if (!isdiv) reg6[0][rank] = myrel;                 // rel in sorted order
        else ((int*)reg6[1])[tid] = (rank >= Nn - TOPK) ? 1 : 0;   // top-10 mask
    }
    __syncthreads();

    // ---------------- prefix scan (warp shuffles), build TB
    {
        float x = ssort[tid];
        float inc = x;
#pragma unroll
        for (int o = 1; o < 32; o <<= 1) {
            float up = __shfl_up_sync(0xffffffffu, inc, o);
            if (lane >= o) inc += up;
        }
        if (lane == 31) swarp[w] = inc;
        __syncthreads();
        if (w == 0) {
            float t = (lane < 16) ? swarp[lane] : 0.f;
#pragma unroll
            for (int o = 1; o < 16; o <<= 1) {
                float up = __shfl_up_sync(0xffffffffu, t, o);
                if (lane >= o) t += up;
            }
            if (lane < 16) swarp[lane] = t;
        }
        __syncthreads();
        float offs = (w > 0) ? swarp[w - 1] : 0.f;
        float tot = swarp[15];
        float incl = inc + offs;
        float pre = incl - x;
        float A = (float)(2 * tid - Nn) * x + tot - 2.f * pre;
        sTB[tid] = make_float2(x * C10L2E, -A * C10L2E);
    }
    __syncthreads();

    // ---------------- per-row band: analytic peak j* = N-1-r, two binary searches
    float my_v = (float)(Nn - 1 - 2 * tid);
    float my_mxx;
    int my_lo, my_hi;
    {
        int jstar = Nn - 1 - tid;
        float2 tp = sTB[jstar];
        my_mxx = fmaf(my_v, tp.x, tp.y);       // exact row max (x unimodal, peak at jstar)
        float thr = my_mxx - THRX;
        int a0 = 0, b0 = jstar;                // x nondecreasing on [0, jstar]
        while (a0 < b0) {
            int m = (a0 + b0) >> 1;
            float2 t = sTB[m];
            if (fmaf(my_v, t.x, t.y) >= thr) b0 = m; else a0 = m + 1;
        }
        my_lo = a0;
        a0 = jstar; b0 = Nn - 1;               // x nonincreasing on [jstar, N-1]
        while (a0 < b0) {
            int m = (a0 + b0 + 1) >> 1;
            float2 t = sTB[m];
            if (fmaf(my_v, t.x, t.y) >= thr) a0 = m; else b0 = m - 1;
        }
        my_hi = a0 + 1;
        slo[tid] = my_lo; shi[tid] = my_hi;
    }
    __syncthreads();

    // ---------------- column row-ranges by scatter inversion (lo/hi monotone)
    {
        int prev = (tid == 0) ? Nn : slo[tid - 1];         // rlo(j) = tid for j in [lo, prev)
        for (int j = my_lo; j < prev; j++) srlo[j] = tid;
        int nxt = (tid == Nn - 1) ? 0 : shi[tid + 1];      // rhi(j) = tid for j in [nxt, hi)
        for (int j = nxt; j < my_hi; j++) srhi[j] = tid;
    }
    __syncthreads();

    int my_rlo = srlo[tid], my_rhi = srhi[tid];
    int my_lo8 = my_lo & ~7;
    int my_i0  = my_rlo & ~7;
    float2 my_tb = sTB[tid];
    float my_r = 1.0f, my_inv = 1.0f;

    // ---------------- sweeps
    // sweep 0: col#1 (r=1).  sweeps 1..4: row#k + col#(k+1).
    // sweep 5 (div only): weighted row#5 + approx_rank.  ndcg row#5 in tail.
    int nsweep = isdiv ? 6 : 5;
    for (int sweep = 0; sweep < nsweep; sweep++) {
        bool first = (sweep == 0);
        bool last6 = (sweep == 5);
        // ---- pass A: thread-per-row, 8-wide float4 body (MLP ~6)
        {
            float a0 = 0.f, a1 = 0.f, a2 = 0.f, a3 = 0.f;
            if (first) {
                for (int j = my_lo8; j < my_hi; j += 8) {
                    float4 t01 = *(const float4*)&sTB[j];
                    float4 t23 = *(const float4*)&sTB[j + 2];
                    float4 t45 = *(const float4*)&sTB[j + 4];
                    float4 t67 = *(const float4*)&sTB[j + 6];
                    a0 += ex2(fmaf(my_v, t01.x, t01.y) - my_mxx)
                        + ex2(fmaf(my_v, t45.x, t45.y) - my_mxx);
                    a1 += ex2(fmaf(my_v, t01.z, t01.w) - my_mxx)
                        + ex2(fmaf(my_v, t45.z, t45.w) - my_mxx);
                    a2 += ex2(fmaf(my_v, t23.x, t23.y) - my_mxx)
                        + ex2(fmaf(my_v, t67.x, t67.y) - my_mxx);
                    a3 += ex2(fmaf(my_v, t23.z, t23.w) - my_mxx)
                        + ex2(fmaf(my_v, t67.z, t67.w) - my_mxx);
                }
            } else {
                for (int j = my_lo8; j < my_hi; j += 8) {
                    float4 t01 = *(const float4*)&sTB[j];
                    float4 t23 = *(const float4*)&sTB[j + 2];
                    float4 t45 = *(const float4*)&sTB[j + 4];
                    float4 t67 = *(const float4*)&sTB[j + 6];
                    float4 cA  = *(const float4*)&sc[j];
                    float4 cB  = *(const float4*)&sc[j + 4];
                    a0 = fmaf(cA.x, ex2(fmaf(my_v, t01.x, t01.y) - my_mxx), a0);
                    a1 = fmaf(cA.y, ex2(fmaf(my_v, t01.z, t01.w) - my_mxx), a1);
                    a2 = fmaf(cA.z, ex2(fmaf(my_v, t23.x, t23.y) - my_mxx), a2);
                    a3 = fmaf(cA.w, ex2(fmaf(my_v, t23.z, t23.w) - my_mxx), a3);
                    a0 = fmaf(cB.x, ex2(fmaf(my_v, t45.x, t45.y) - my_mxx), a0);
                    a1 = fmaf(cB.y, ex2(fmaf(my_v, t45.z, t45.w) - my_mxx), a1);
                    a2 = fmaf(cB.z, ex2(fmaf(my_v, t67.x, t67.y) - my_mxx), a2);
                    a3 = fmaf(cB.w, ex2(fmaf(my_v, t67.z, t67.w) - my_mxx), a3);
                }
            }
            float racc = (a0 + a1) + (a2 + a3);
            float rho;
            if (first) {
                my_inv = 1.f / racc;           // racc >= 1 (exp at jstar == 1)
                rho = my_inv;
            } else {
                float rowsum = my_inv * racc;
                float rn = (rowsum == 0.f) ? 0.f : (my_r / fmaxf(my_r * rowsum, EPSV));
                if (!last6) my_r = rn;
                rho = rn * my_inv;
                if (last6) rho *= (float)(Nn - tid);   // w_i = N - i
            }
            srm[tid] = make_float2(rho, my_mxx);
        }
        __syncthreads();
        // ---- pass B: thread-per-column, exact row range, 8-wide float4 body
        {
            float a0 = 0.f, a1 = 0.f, a2 = 0.f, a3 = 0.f;
            float vf0 = (float)(Nn - 1 - 2 * my_i0);
            for (int i = my_i0; i <= my_rhi; i += 8) {
                float4 r01 = *(const float4*)&srm[i];
                float4 r23 = *(const float4*)&srm[i + 2];
                float4 r45 = *(const float4*)&srm[i + 4];
                float4 r67 = *(const float4*)&srm[i + 6];
                a0 = fmaf(r01.x, ex2(fmaf(vf0,        my_tb.x, my_tb.y) - r01.y), a0);
                a1 = fmaf(r01.z, ex2(fmaf(vf0 -  2.f, my_tb.x, my_tb.y) - r01.w), a1);
                a2 = fmaf(r23.x, ex2(fmaf(vf0 -  4.f, my_tb.x, my_tb.y) - r23.y), a2);
                a3 = fmaf(r23.z, ex2(fmaf(vf0 -  6.f, my_tb.x, my_tb.y) - r23.w), a3);
                a0 = fmaf(r45.x, ex2(fmaf(vf0 -  8.f, my_tb.x, my_tb.y) - r45.y), a0);
                a1 = fmaf(r45.z, ex2(fmaf(vf0 - 10.f, my_tb.x, my_tb.y) - r45.w), a1);
                a2 = fmaf(r67.x, ex2(fmaf(vf0 - 12.f, my_tb.x, my_tb.y) - r67.y), a2);
                a3 = fmaf(r67.z, ex2(fmaf(vf0 - 14.f, my_tb.x, my_tb.y) - r67.w), a3);
                vf0 -= 16.f;
            }
            float cac = (a0 + a1) + (a2 + a3);
            if (!last6) {
                float c = first ? 1.f : sc[tid];
                sc[tid] = (cac == 0.f) ? 0.f : (c / fmaxf(c * cac, EPSV));
            } else {
                float arr = sc[tid] * cac;     // approx_rank (sorted col)
                reg6[0][sidx[tid]] = 1.f / (1.f + ex2(((float)(Nn - TOPK) - arr) * L2E));
            }
        }
        __syncthreads();
    }

    // ---------------- finals
    if (!isdiv) {
        // row#5 for rows 0..9 only, fused with approx_rel (thread-per-row)
        if (tid < TOPK) {
            float racc = 0.f, ra = 0.f;
            for (int j = my_lo8; j < my_hi; j += 2) {
                float4 t01 = *(const float4*)&sTB[j];
                float c0 = sc[j], c1 = sc[j + 1];
                float e0 = c0 * ex2(fmaf(my_v, t01.x, t01.y) - my_mxx);
                float e1 = c1 * ex2(fmaf(my_v, t01.z, t01.w) - my_mxx);
                racc += e0 + e1;
                ra = fmaf(e0, reg6[0][j], ra);
                ra = fmaf(e1, (j + 1 < Nn) ? reg6[0][j + 1] : 0.f, ra);
            }
            float rowsum = my_inv * racc;
            float rn = (rowsum == 0.f) ? 0.f : (my_r / fmaxf(my_r * rowsum, EPSV));
            sarel[tid] = rn * my_inv * ra;
        }
        if (w == 2) warp_top10_vals(reg6[1], lane, st10b);   // top-10 of relevance
        __syncthreads();
        if (tid == 0) {
            float da = 0.f, dm = 0.f, db = 0.f;
            for (int t = 0; t < TOPK; t++) {
                float disc = log2f((float)(t + 2));
                da += (exp2f(sarel[t]) - 1.f) / disc;
                dm += (exp2f(reg6[0][Nn - 1 - t]) - 1.f) / disc;  // rel at top-10 scores
                db += (exp2f(st10b[t]) - 1.f) / disc;
            }
            out[u]      = da / db;
            out[Uu + u] = dm / db;
        }
    } else {
        // item phase: warp per 32 items, lane owns feats {2l, 2l+1}
        float gx = 0.f, gy = 0.f, hx = 0.f, hy = 0.f;
        float s1 = 0.f, s2 = 0.f, q = 0.f, qh = 0.f;
        for (int ii = 0; ii < 32; ii++) {
            int j = (w << 5) + ii;
            const float2 xy = *(const float2*)(batch + ((size_t)(u * Nn + j)) * Ff + 2 * lane);
            float nr = xy.x * xy.x + xy.y * xy.y;
            nr = warp_sum(nr);
            float nrm = sqrtf(nr);
            float inv = 1.f / fmaxf(nrm, 1e-8f);
            float nn = nr * inv * inv;
            float a = reg6[0][j];
            gx += a * xy.x * inv; gy += a * xy.y * inv;
            int m = ((int*)reg6[1])[j];
            if (m) { hx += xy.x * inv; hy += xy.y * inv; }
            if (lane == 0) {
                s1 += a; s2 += a * a; q += a * a * nn;
                if (m) qh += nn;
            }
        }
        sgp[w][2 * lane] = gx; sgp[w][2 * lane + 1] = gy;
        shp[w][2 * lane] = hx; shp[w][2 * lane + 1] = hy;
        if (lane == 0) {
            sscal[w][0] = s1; sscal[w][1] = s2; sscal[w][2] = q; sscal[w][3] = qh;
        }
        __syncthreads();
        if (tid < FUF) {
            float gf = 0.f, hf = 0.f;
#pragma unroll
            for (int qq = 0; qq < 16; qq++) { gf += sgp[qq][tid]; hf += shp[qq][tid]; }
            sfin[tid] = gf * gf;
            sfin[FUF + tid] = hf * hf;
        }
        __syncthreads();
        if (tid == 0) {
            float G2 = 0.f, H2 = 0.f;
            for (int f = 0; f < FUF; f++) { G2 += sfin[f]; H2 += sfin[FUF + f]; }
            float S1 = 0.f, S2v = 0.f, Q = 0.f, Qh = 0.f;
            for (int qq = 0; qq < 16; qq++) {
                S1 += sscal[qq][0]; S2v += sscal[qq][1];
                Q  += sscal[qq][2]; Qh  += sscal[qq][3];
            }
            float denomA = S1 * S1 - S2v;
            out[2 * Uu + u] = 1.f - (G2 - Q) / denomA;
            out[3 * Uu + u] = (45.f - 0.5f * (H2 - Qh)) / 45.f;
        }
    }
}

// ---------------------------------------------------------------------------
extern "C" void kernel_launch(void* const* d_in, const int* in_sizes, int n_in,
                              void* d_out, int out_size) {
    const float* batch  = (const float*)d_in[0];
    const float* s_div  = (const float*)d_in[1];
    const float* s_ndcg = (const float*)d_in[2];
    const float* rel    = (const float*)d_in[3];
    float* out = (float*)d_out;

    mega_kernel<<<256, 512>>>(batch, s_div, s_ndcg, rel, out);
}